// round 10
// baseline (speedup 1.0000x reference)
#include <cuda_runtime.h>
#include <math.h>

#define HW 4096
#define NC 256
#define NB 4
#define NBG 512      // convapply grid (co-resident at 4 blocks/SM: 592 >= 512)

// ---- device scratch (16B-aligned: accessed via float4) ----
__device__ __align__(16) float g_ch_avg[NB*NC];
__device__ __align__(16) float g_ch_max[NB*NC];
__device__ __align__(16) float g_ch_att[NB*NC];
__device__ __align__(16) float g_sp_avg[NB*HW];
__device__ __align__(16) float g_sp_max[NB*HW];
// attention scratch (only used when gamma != 0; never in this bench)
__device__ __align__(16) float g_q[NB*32*HW];
__device__ __align__(16) float g_k[NB*32*HW];
__device__ __align__(16) float g_v[NB*NC*HW];
__device__ unsigned g_bar_cnt = 0;
__device__ unsigned g_bar_gen = 0;

__device__ __forceinline__ void gbarrier(unsigned* cnt, unsigned* gen, unsigned nb) {
    __syncthreads();
    if (threadIdx.x == 0) {
        unsigned g = *(volatile unsigned*)gen;
        __threadfence();
        unsigned a = atomicAdd(cnt, 1u);
        if (a == nb - 1u) {
            *(volatile unsigned*)cnt = 0u;
            __threadfence();
            atomicAdd(gen, 1u);
        } else {
            while (*(volatile unsigned*)gen == g) { }
            __threadfence();
        }
    }
    __syncthreads();
}

// K1: per-(b,c) spatial mean & max. 1024 blocks x 256 thr; 1 row per block;
// 4 independent float4 loads per thread; shuffle reduce (no smem tree).
__global__ void k_chstats(const float* __restrict__ x) {
    int t = threadIdx.x, lane = t & 31, wid = t >> 5;
    int bc = blockIdx.x;
    const float4* xr = reinterpret_cast<const float4*>(x + (size_t)bc * HW);
    float s = 0.f, m = -1e30f;
#pragma unroll
    for (int j = 0; j < 4; j++) {
        float4 v = xr[t + j * 256];
        s += v.x + v.y + v.z + v.w;
        m = fmaxf(m, fmaxf(fmaxf(v.x, v.y), fmaxf(v.z, v.w)));
    }
#pragma unroll
    for (int o = 16; o > 0; o >>= 1) {
        s += __shfl_down_sync(0xffffffffu, s, o);
        m = fmaxf(m, __shfl_down_sync(0xffffffffu, m, o));
    }
    __shared__ float ws[8], wm[8];
    if (lane == 0) { ws[wid] = s; wm[wid] = m; }
    __syncthreads();
    if (t == 0) {
        float S = 0.f, M = -1e30f;
#pragma unroll
        for (int w = 0; w < 8; w++) { S += ws[w]; M = fmaxf(M, wm[w]); }
        g_ch_avg[bc] = S * (1.f / HW);
        g_ch_max[bc] = M;
    }
}

// K2: inline channel-MLP (redundant per block) + per-pixel channel mean/max
// of (x * ch_att). 512 blocks: b = blk>>7, 32 pixels per block.
// Thread layout: pq = t&7 (4-px quad), cgrp = t>>3 (8 channels each).
__global__ void k_spstats(const float* __restrict__ x,
                          const float* __restrict__ w1, const float* __restrict__ w2) {
    int t   = threadIdx.x;
    int blk = blockIdx.x;
    int b   = blk >> 7;
    __shared__ float sa_[256], sx_[256], sh[16];
    __shared__ __align__(16) float att[256];
    __shared__ float4 ssum[256], smx[256];

    sa_[t] = g_ch_avg[b * 256 + t];
    sx_[t] = g_ch_max[b * 256 + t];
    __syncthreads();
    {
        int wid = t >> 5, lid = t & 31;
#pragma unroll
        for (int u = 0; u < 2; u++) {
            int h = wid * 2 + u;
            const float* wr = w1 + h * 256;
            float ha = 0.f, hm = 0.f;
#pragma unroll
            for (int k = 0; k < 8; k++) {
                int c = k * 32 + lid;
                float wv = wr[c];
                ha += sa_[c] * wv; hm += sx_[c] * wv;
            }
#pragma unroll
            for (int o = 16; o > 0; o >>= 1) {
                ha += __shfl_down_sync(0xffffffffu, ha, o);
                hm += __shfl_down_sync(0xffffffffu, hm, o);
            }
            if (lid == 0) sh[h] = fmaxf(ha, 0.f) + fmaxf(hm, 0.f);
        }
    }
    __syncthreads();
    {
        float o = 0.f;
        const float* w2r = w2 + t * 16;
#pragma unroll
        for (int r = 0; r < 16; r++) o += sh[r] * w2r[r];
        att[t] = 1.f / (1.f + expf(-o));
        if ((blk & 127) == 0) g_ch_att[b * 256 + t] = att[t];
    }
    __syncthreads();

    int pq = t & 7, cgrp = t >> 3;
    int p0 = (blk & 127) * 32 + pq * 4;
    int c0 = cgrp * 8;
    const float* xb = x + ((size_t)b << 20) + p0;
    float4 s = {0.f, 0.f, 0.f, 0.f};
    float4 m = {-1e30f, -1e30f, -1e30f, -1e30f};
#pragma unroll
    for (int k = 0; k < 8; k++) {
        float a = att[c0 + k];
        float4 v = *reinterpret_cast<const float4*>(xb + ((size_t)(c0 + k) << 12));
        v.x *= a; v.y *= a; v.z *= a; v.w *= a;
        s.x += v.x; s.y += v.y; s.z += v.z; s.w += v.w;
        m.x = fmaxf(m.x, v.x); m.y = fmaxf(m.y, v.y);
        m.z = fmaxf(m.z, v.z); m.w = fmaxf(m.w, v.w);
    }
    ssum[t] = s; smx[t] = m; __syncthreads();
    if (t < 8) {
        float4 ts = {0.f, 0.f, 0.f, 0.f};
        float4 tm = {-1e30f, -1e30f, -1e30f, -1e30f};
#pragma unroll
        for (int g = 0; g < 32; g++) {
            float4 a = ssum[g * 8 + t], q = smx[g * 8 + t];
            ts.x += a.x; ts.y += a.y; ts.z += a.z; ts.w += a.w;
            tm.x = fmaxf(tm.x, q.x); tm.y = fmaxf(tm.y, q.y);
            tm.z = fmaxf(tm.z, q.z); tm.w = fmaxf(tm.w, q.w);
        }
        ts.x *= (1.f / 256.f); ts.y *= (1.f / 256.f);
        ts.z *= (1.f / 256.f); ts.w *= (1.f / 256.f);
        int p = (blk & 127) * 32 + t * 4;
        *reinterpret_cast<float4*>(&g_sp_avg[(b << 12) + p]) = ts;
        *reinterpret_cast<float4*>(&g_sp_max[(b << 12) + p]) = tm;
    }
}

// K3: fused 7x7 conv (+sigmoid) + final apply; grid (4,16,8) = 512 blocks,
// 32-channel groups. Then (gamma!=0 only) full non-local attention behind an
// internal grid barrier (all 512 blocks co-resident at 4/SM).
__global__ void __launch_bounds__(256, 4) k_convapply(
        const float* __restrict__ x, const float* __restrict__ w_sp,
        float* __restrict__ out,
        const float* __restrict__ wq, const float* __restrict__ bq,
        const float* __restrict__ wk, const float* __restrict__ bk,
        const float* __restrict__ wv, const float* __restrict__ bv,
        const float* __restrict__ gamma) {
    int b = blockIdx.x, tile = blockIdx.y, cg = blockIdx.z;
    int t = threadIdx.x;
    __shared__ __align__(16) float satt[256];
    __shared__ float w[98], sa[10][64], sx[10][64], catt[32];
    __shared__ __align__(16) float pool[8192];   // gamma path: xs / sbuf
    __shared__ float red[256], qv[32];

    if (t < 98) w[t] = w_sp[t];
    if (t >= 128 && t < 160) catt[t - 128] = g_ch_att[b * 256 + cg * 32 + (t - 128)];
    for (int i = t; i < 640; i += 256) {
        int r = i >> 6, cx = i & 63;
        int gy = tile * 4 + r - 3;
        float va = 0.f, vm = 0.f;
        if ((unsigned)gy < 64u) {
            va = g_sp_avg[b * 4096 + gy * 64 + cx];
            vm = g_sp_max[b * 4096 + gy * 64 + cx];
        }
        sa[r][cx] = va; sx[r][cx] = vm;
    }
    __syncthreads();
    {
        int r = t >> 6, cx = t & 63;
        float acc = 0.f;
#pragma unroll
        for (int ky = 0; ky < 7; ky++) {
#pragma unroll
            for (int kx = 0; kx < 7; kx++) {
                int ix = cx + kx - 3;
                if ((unsigned)ix < 64u) {
                    acc += w[ky * 7 + kx] * sa[r + ky][ix]
                         + w[49 + ky * 7 + kx] * sx[r + ky][ix];
                }
            }
        }
        satt[t] = 1.f / (1.f + expf(-acc));
    }
    __syncthreads();
    {
        const float* xb = x   + ((size_t)b << 20) + ((size_t)cg << 17) + tile * 256;
        float*       ob = out + ((size_t)b << 20) + ((size_t)cg << 17) + tile * 256;
#pragma unroll
        for (int k = 0; k < 8; k++) {
            int idx = k * 256 + t;
            int cl = idx >> 6, pquad = idx & 63;
            float a = catt[cl];
            float4 sv = *reinterpret_cast<const float4*>(&satt[pquad * 4]);
            float4 xv = *reinterpret_cast<const float4*>(xb + ((size_t)cl << 12) + pquad * 4);
            float4 o;
            o.x = xv.x * a * sv.x; o.y = xv.y * a * sv.y;
            o.z = xv.z * a * sv.z; o.w = xv.w * a * sv.w;
            *reinterpret_cast<float4*>(ob + ((size_t)cl << 12) + pquad * 4) = o;
        }
    }

    // ---- gamma != 0 path (exact; skipped entirely when gamma == 0) ----
    float g = gamma[0];
    if (g == 0.f) return;
    int bid = blockIdx.x + NB * (blockIdx.y + 16 * blockIdx.z);   // 0..511

    gbarrier(&g_bar_cnt, &g_bar_gen, NBG);   // out fully written

    // phase A: q/k/v projections of out (x2)
    for (int wkid = bid; wkid < 128 * NB; wkid += NBG) {
        int chunk = wkid & 127, bb = wkid >> 7;
        __syncthreads();
        {
            const float* src = out + ((size_t)(bb * 256 + t)) * HW + chunk * 32;
            for (int p = 0; p < 32; p += 4) {
                float4 v = *reinterpret_cast<const float4*>(src + p);
                pool[t * 32 + p] = v.x; pool[t * 32 + p + 1] = v.y;
                pool[t * 32 + p + 2] = v.z; pool[t * 32 + p + 3] = v.w;
            }
        }
        __syncthreads();
        for (int k = 0; k < 40; k++) {
            int oi = k * 256 + t;
            int o = oi >> 5, p = oi & 31;
            const float* wr; float bias; float* dst; int row;
            if (o < 32)      { wr = wq + o * 256;        bias = bq[o];      dst = g_q; row = bb * 32 + o; }
            else if (o < 64) { int r = o - 32; wr = wk + r * 256; bias = bk[r]; dst = g_k; row = bb * 32 + r; }
            else             { int r = o - 64; wr = wv + r * 256; bias = bv[r]; dst = g_v; row = bb * 256 + r; }
            float acc = bias;
            for (int c = 0; c < 256; c++) acc += wr[c] * pool[c * 32 + p];
            dst[(size_t)row * HW + chunk * 32 + p] = acc;
        }
    }
    gbarrier(&g_bar_cnt, &g_bar_gen, NBG);

    // phase B: per (b, query i) softmax attention
    for (int bi = bid; bi < NB * HW; bi += NBG) {
        int bb = bi >> 12, i = bi & 4095;
        if (t < 32) qv[t] = g_q[(bb * 32 + t) * HW + i];
        __syncthreads();
        float lm = -1e30f;
        for (int j = t; j < 4096; j += 256) {
            float s = 0.f;
#pragma unroll
            for (int d = 0; d < 32; d++) s += qv[d] * g_k[(bb * 32 + d) * HW + j];
            pool[j] = s; lm = fmaxf(lm, s);
        }
        red[t] = lm; __syncthreads();
        for (int o = 128; o > 0; o >>= 1) {
            if (t < o) red[t] = fmaxf(red[t], red[t + o]);
            __syncthreads();
        }
        float m = red[0]; __syncthreads();
        float ls = 0.f;
        for (int j = t; j < 4096; j += 256) {
            float e = expf(pool[j] - m);
            pool[j] = e; ls += e;
        }
        red[t] = ls; __syncthreads();
        for (int o = 128; o > 0; o >>= 1) {
            if (t < o) red[t] += red[t + o];
            __syncthreads();
        }
        float inv = 1.f / red[0]; __syncthreads();
        float acc = 0.f;
        const float* vr = g_v + (size_t)(bb * 256 + t) * HW;
        for (int j = 0; j < 4096; j++) acc += vr[j] * pool[j];
        out[(bb * 256 + t) * HW + i] += g * acc * inv;
        __syncthreads();
    }
}

extern "C" void kernel_launch(void* const* d_in, const int* in_sizes, int n_in,
                              void* d_out, int out_size) {
    const float* x     = (const float*)d_in[0];
    const float* w1    = (const float*)d_in[1];
    const float* w2    = (const float*)d_in[2];
    const float* w_sp  = (const float*)d_in[3];
    const float* wq    = (const float*)d_in[4];
    const float* bq    = (const float*)d_in[5];
    const float* wk    = (const float*)d_in[6];
    const float* bk    = (const float*)d_in[7];
    const float* wv    = (const float*)d_in[8];
    const float* bv    = (const float*)d_in[9];
    const float* gamma = (const float*)d_in[10];
    float* out = (float*)d_out;

    k_chstats<<<1024, 256>>>(x);
    k_spstats<<<512, 256>>>(x, w1, w2);
    k_convapply<<<dim3(NB, 16, 8), 256>>>(x, w_sp, out, wq, bq, wk, bk, wv, bv, gamma);
}

// round 11
// speedup vs baseline: 1.2023x; 1.2023x over previous
#include <cuda_runtime.h>
#include <math.h>
#include <stdint.h>

#define HW 4096
#define NC 256
#define NB 4
#define NBG 256      // convapply grid (wave-1 co-resident at 2 blocks/SM)

// ---- device scratch (16B-aligned: accessed via float4) ----
__device__ __align__(16) float g_ch_avg[NB*NC];
__device__ __align__(16) float g_ch_max[NB*NC];
__device__ __align__(16) float g_ch_att[NB*NC];
__device__ __align__(16) float g_sp_avg[NB*HW];
__device__ __align__(16) float g_sp_max[NB*HW];
// attention scratch (only used when gamma != 0; never in this bench)
__device__ __align__(16) float g_q[NB*32*HW];
__device__ __align__(16) float g_k[NB*32*HW];
__device__ __align__(16) float g_v[NB*NC*HW];
__device__ unsigned g_bar_cnt = 0;
__device__ unsigned g_bar_gen = 0;

__device__ __forceinline__ void gbarrier(unsigned* cnt, unsigned* gen, unsigned nb) {
    __syncthreads();
    if (threadIdx.x == 0) {
        unsigned g = *(volatile unsigned*)gen;
        __threadfence();
        unsigned a = atomicAdd(cnt, 1u);
        if (a == nb - 1u) {
            *(volatile unsigned*)cnt = 0u;
            __threadfence();
            atomicAdd(gen, 1u);
        } else {
            while (*(volatile unsigned*)gen == g) { }
            __threadfence();
        }
    }
    __syncthreads();
}

__device__ __forceinline__ uint32_t smem_u32(const void* p) {
    uint32_t a;
    asm("{ .reg .u64 t; cvta.to.shared.u64 t, %1; cvt.u32.u64 %0, t; }" : "=r"(a) : "l"(p));
    return a;
}

// K1: per-(b,c) spatial mean & max via ONE 32KB bulk copy per block (2 rows),
// then smem reduce. 512 blocks x 256 thr. Bypasses the per-LDG issue path.
__global__ void k_chstats(const float* __restrict__ x) {
    __shared__ __align__(128) float buf[8192];        // 32 KB = 2 rows
    __shared__ __align__(8) unsigned long long mbar;
    __shared__ float ws[8], wm[8];
    int t = threadIdx.x, lane = t & 31, wid = t >> 5;
    uint32_t mb = smem_u32(&mbar);
    if (t == 0) {
        asm volatile("mbarrier.init.shared.b64 [%0], %1;" :: "r"(mb), "r"(1u) : "memory");
    }
    __syncthreads();
    if (t == 0) {
        asm volatile("mbarrier.arrive.expect_tx.shared.b64 _, [%0], %1;"
                     :: "r"(mb), "r"(32768u) : "memory");
        asm volatile("cp.async.bulk.shared::cta.global.mbarrier::complete_tx::bytes "
                     "[%0], [%1], %2, [%3];"
                     :: "r"(smem_u32(buf)),
                        "l"(x + (size_t)blockIdx.x * 8192),
                        "r"(32768u), "r"(mb) : "memory");
    }
    // wait (parity 0)
    {
        uint32_t done;
        asm volatile("{\n\t.reg .pred p;\n\t"
                     "mbarrier.try_wait.parity.acquire.cta.shared::cta.b64 p, [%1], %2;\n\t"
                     "selp.b32 %0, 1, 0, p;\n\t}"
                     : "=r"(done) : "r"(mb), "r"(0u) : "memory");
        if (!done) {
            asm volatile("{\n\t.reg .pred P1;\n\t"
                         "WL_%=:\n\t"
                         "mbarrier.try_wait.parity.acquire.cta.shared::cta.b64 P1, [%0], %1, 0x989680;\n\t"
                         "@P1 bra.uni WD_%=;\n\t"
                         "bra.uni WL_%=;\n\t"
                         "WD_%=:\n\t}" :: "r"(mb), "r"(0u) : "memory");
        }
    }
    // reduce: warps 0-3 -> row 0, warps 4-7 -> row 1
    int half = t >> 7, i = t & 127;
    const float4* br = reinterpret_cast<const float4*>(buf + half * 4096);
    float s = 0.f, m = -1e30f;
#pragma unroll
    for (int j = 0; j < 8; j++) {
        float4 v = br[i + j * 128];
        s += v.x + v.y + v.z + v.w;
        m = fmaxf(m, fmaxf(fmaxf(v.x, v.y), fmaxf(v.z, v.w)));
    }
#pragma unroll
    for (int o = 16; o > 0; o >>= 1) {
        s += __shfl_down_sync(0xffffffffu, s, o);
        m = fmaxf(m, __shfl_down_sync(0xffffffffu, m, o));
    }
    if (lane == 0) { ws[wid] = s; wm[wid] = m; }
    __syncthreads();
    if ((t & 127) == 0) {
        int base = half * 4;
        float S = ws[base] + ws[base + 1] + ws[base + 2] + ws[base + 3];
        float M = fmaxf(fmaxf(wm[base], wm[base + 1]), fmaxf(wm[base + 2], wm[base + 3]));
        g_ch_avg[blockIdx.x * 2 + half] = S * (1.f / HW);
        g_ch_max[blockIdx.x * 2 + half] = M;
    }
}

// K2: inline channel-MLP + per-pixel channel mean/max of (x * ch_att).
// 256 blocks: b = blk>>6, 64 pixels per block. (R9 known-good form.)
__global__ void k_spstats(const float* __restrict__ x,
                          const float* __restrict__ w1, const float* __restrict__ w2) {
    int t   = threadIdx.x;
    int blk = blockIdx.x;
    int b   = blk >> 6;
    __shared__ float sa_[256], sx_[256], sh[16];
    __shared__ __align__(16) float att[256];
    __shared__ float4 ssum[256], smx[256];

    sa_[t] = g_ch_avg[b * 256 + t];
    sx_[t] = g_ch_max[b * 256 + t];
    __syncthreads();
    {
        int wid = t >> 5, lid = t & 31;
#pragma unroll
        for (int u = 0; u < 2; u++) {
            int h = wid * 2 + u;
            const float* wr = w1 + h * 256;
            float ha = 0.f, hm = 0.f;
#pragma unroll
            for (int k = 0; k < 8; k++) {
                int c = k * 32 + lid;
                float wv = wr[c];
                ha += sa_[c] * wv; hm += sx_[c] * wv;
            }
#pragma unroll
            for (int o = 16; o > 0; o >>= 1) {
                ha += __shfl_down_sync(0xffffffffu, ha, o);
                hm += __shfl_down_sync(0xffffffffu, hm, o);
            }
            if (lid == 0) sh[h] = fmaxf(ha, 0.f) + fmaxf(hm, 0.f);
        }
    }
    __syncthreads();
    {
        float o = 0.f;
        const float* w2r = w2 + t * 16;
#pragma unroll
        for (int r = 0; r < 16; r++) o += sh[r] * w2r[r];
        att[t] = 1.f / (1.f + expf(-o));
        if ((blk & 63) == 0) g_ch_att[b * 256 + t] = att[t];
    }
    __syncthreads();

    int pq = t & 15, cgrp = t >> 4;
    int p0 = (blk & 63) * 64 + pq * 4;
    int c0 = cgrp * 16;
    const float* xb = x + ((size_t)b << 20) + p0;
    float4 s = {0.f, 0.f, 0.f, 0.f};
    float4 m = {-1e30f, -1e30f, -1e30f, -1e30f};
#pragma unroll
    for (int k = 0; k < 16; k++) {
        float a = att[c0 + k];
        float4 v = *reinterpret_cast<const float4*>(xb + ((size_t)(c0 + k) << 12));
        v.x *= a; v.y *= a; v.z *= a; v.w *= a;
        s.x += v.x; s.y += v.y; s.z += v.z; s.w += v.w;
        m.x = fmaxf(m.x, v.x); m.y = fmaxf(m.y, v.y);
        m.z = fmaxf(m.z, v.z); m.w = fmaxf(m.w, v.w);
    }
    ssum[t] = s; smx[t] = m; __syncthreads();
    if (t < 16) {
        float4 ts = {0.f, 0.f, 0.f, 0.f};
        float4 tm = {-1e30f, -1e30f, -1e30f, -1e30f};
#pragma unroll
        for (int g = 0; g < 16; g++) {
            float4 a = ssum[g * 16 + t], q = smx[g * 16 + t];
            ts.x += a.x; ts.y += a.y; ts.z += a.z; ts.w += a.w;
            tm.x = fmaxf(tm.x, q.x); tm.y = fmaxf(tm.y, q.y);
            tm.z = fmaxf(tm.z, q.z); tm.w = fmaxf(tm.w, q.w);
        }
        ts.x *= (1.f / 256.f); ts.y *= (1.f / 256.f);
        ts.z *= (1.f / 256.f); ts.w *= (1.f / 256.f);
        int p = (blk & 63) * 64 + t * 4;
        *reinterpret_cast<float4*>(&g_sp_avg[(b << 12) + p]) = ts;
        *reinterpret_cast<float4*>(&g_sp_max[(b << 12) + p]) = tm;
    }
}

// K3: fused 7x7 conv (+sigmoid) + final apply (R9 known-good form), then
// (gamma!=0 only) full non-local attention behind an internal grid barrier.
__global__ void __launch_bounds__(256, 2) k_convapply(
        const float* __restrict__ x, const float* __restrict__ w_sp,
        float* __restrict__ out,
        const float* __restrict__ wq, const float* __restrict__ bq,
        const float* __restrict__ wk, const float* __restrict__ bk,
        const float* __restrict__ wv, const float* __restrict__ bv,
        const float* __restrict__ gamma) {
    int b = blockIdx.x, tile = blockIdx.y, cg = blockIdx.z;
    int t = threadIdx.x;
    __shared__ __align__(16) float satt[256];
    __shared__ float w[98], sa[10][64], sx[10][64], catt[64];
    __shared__ __align__(16) float pool[8192];   // gamma path: xs / sbuf
    __shared__ float red[256], qv[32];

    if (t < 98) w[t] = w_sp[t];
    if (t >= 128 && t < 192) catt[t - 128] = g_ch_att[b * 256 + cg * 64 + (t - 128)];
    for (int i = t; i < 640; i += 256) {
        int r = i >> 6, cx = i & 63;
        int gy = tile * 4 + r - 3;
        float va = 0.f, vm = 0.f;
        if ((unsigned)gy < 64u) {
            va = g_sp_avg[b * 4096 + gy * 64 + cx];
            vm = g_sp_max[b * 4096 + gy * 64 + cx];
        }
        sa[r][cx] = va; sx[r][cx] = vm;
    }
    __syncthreads();
    {
        int r = t >> 6, cx = t & 63;
        float acc = 0.f;
#pragma unroll
        for (int ky = 0; ky < 7; ky++) {
#pragma unroll
            for (int kx = 0; kx < 7; kx++) {
                int ix = cx + kx - 3;
                if ((unsigned)ix < 64u) {
                    acc += w[ky * 7 + kx] * sa[r + ky][ix]
                         + w[49 + ky * 7 + kx] * sx[r + ky][ix];
                }
            }
        }
        satt[t] = 1.f / (1.f + expf(-acc));
    }
    __syncthreads();
    {
        const float* xb = x   + ((size_t)b << 20) + ((size_t)cg << 18) + tile * 256;
        float*       ob = out + ((size_t)b << 20) + ((size_t)cg << 18) + tile * 256;
#pragma unroll
        for (int k = 0; k < 16; k++) {
            int idx = k * 256 + t;
            int cl = idx >> 6, pquad = idx & 63;
            float a = catt[cl];
            float4 sv = *reinterpret_cast<const float4*>(&satt[pquad * 4]);
            float4 xv = *reinterpret_cast<const float4*>(xb + ((size_t)cl << 12) + pquad * 4);
            float4 o;
            o.x = xv.x * a * sv.x; o.y = xv.y * a * sv.y;
            o.z = xv.z * a * sv.z; o.w = xv.w * a * sv.w;
            *reinterpret_cast<float4*>(ob + ((size_t)cl << 12) + pquad * 4) = o;
        }
    }

    // ---- gamma != 0 path (exact; skipped entirely when gamma == 0) ----
    float g = gamma[0];
    if (g == 0.f) return;
    int bid = blockIdx.x + NB * (blockIdx.y + 16 * blockIdx.z);   // 0..255

    gbarrier(&g_bar_cnt, &g_bar_gen, NBG);   // out fully written

    for (int wkid = bid; wkid < 128 * NB; wkid += NBG) {
        int chunk = wkid & 127, bb = wkid >> 7;
        __syncthreads();
        {
            const float* src = out + ((size_t)(bb * 256 + t)) * HW + chunk * 32;
            for (int p = 0; p < 32; p += 4) {
                float4 v = *reinterpret_cast<const float4*>(src + p);
                pool[t * 32 + p] = v.x; pool[t * 32 + p + 1] = v.y;
                pool[t * 32 + p + 2] = v.z; pool[t * 32 + p + 3] = v.w;
            }
        }
        __syncthreads();
        for (int k = 0; k < 40; k++) {
            int oi = k * 256 + t;
            int o = oi >> 5, p = oi & 31;
            const float* wr; float bias; float* dst; int row;
            if (o < 32)      { wr = wq + o * 256;        bias = bq[o];      dst = g_q; row = bb * 32 + o; }
            else if (o < 64) { int r = o - 32; wr = wk + r * 256; bias = bk[r]; dst = g_k; row = bb * 32 + r; }
            else             { int r = o - 64; wr = wv + r * 256; bias = bv[r]; dst = g_v; row = bb * 256 + r; }
            float acc = bias;
            for (int c = 0; c < 256; c++) acc += wr[c] * pool[c * 32 + p];
            dst[(size_t)row * HW + chunk * 32 + p] = acc;
        }
    }
    gbarrier(&g_bar_cnt, &g_bar_gen, NBG);

    for (int bi = bid; bi < NB * HW; bi += NBG) {
        int bb = bi >> 12, i = bi & 4095;
        if (t < 32) qv[t] = g_q[(bb * 32 + t) * HW + i];
        __syncthreads();
        float lm = -1e30f;
        for (int j = t; j < 4096; j += 256) {
            float s = 0.f;
#pragma unroll
            for (int d = 0; d < 32; d++) s += qv[d] * g_k[(bb * 32 + d) * HW + j];
            pool[j] = s; lm = fmaxf(lm, s);
        }
        red[t] = lm; __syncthreads();
        for (int o = 128; o > 0; o >>= 1) {
            if (t < o) red[t] = fmaxf(red[t], red[t + o]);
            __syncthreads();
        }
        float m = red[0]; __syncthreads();
        float ls = 0.f;
        for (int j = t; j < 4096; j += 256) {
            float e = expf(pool[j] - m);
            pool[j] = e; ls += e;
        }
        red[t] = ls; __syncthreads();
        for (int o = 128; o > 0; o >>= 1) {
            if (t < o) red[t] += red[t + o];
            __syncthreads();
        }
        float inv = 1.f / red[0]; __syncthreads();
        float acc = 0.f;
        const float* vr = g_v + (size_t)(bb * 256 + t) * HW;
        for (int j = 0; j < 4096; j++) acc += vr[j] * pool[j];
        out[(bb * 256 + t) * HW + i] += g * acc * inv;
        __syncthreads();
    }
}

extern "C" void kernel_launch(void* const* d_in, const int* in_sizes, int n_in,
                              void* d_out, int out_size) {
    const float* x     = (const float*)d_in[0];
    const float* w1    = (const float*)d_in[1];
    const float* w2    = (const float*)d_in[2];
    const float* w_sp  = (const float*)d_in[3];
    const float* wq    = (const float*)d_in[4];
    const float* bq    = (const float*)d_in[5];
    const float* wk    = (const float*)d_in[6];
    const float* bk    = (const float*)d_in[7];
    const float* wv    = (const float*)d_in[8];
    const float* bv    = (const float*)d_in[9];
    const float* gamma = (const float*)d_in[10];
    float* out = (float*)d_out;

    k_chstats<<<512, 256>>>(x);
    k_spstats<<<256, 256>>>(x, w1, w2);
    k_convapply<<<dim3(NB, 16, 4), 256>>>(x, w_sp, out, wq, bq, wk, bk, wv, bv, gamma);
}